// round 6
// baseline (speedup 1.0000x reference)
#include <cuda_runtime.h>
#include <cstdint>

#define BSZ    256
#define BOND   5
#define NDIM   128
#define ATOM   64
#define UNITS  128
#define THREADS 256
#define MHALF  64          // M rows per CTA (sample split in half)

// smem float-word pitches (conflict-free fragment access)
#define P_FT 132   // F^T  [d=64][n=128]   B-op: (nt*8+r4)*132 + c4 -> r4*4+c4 distinct
#define P_AC 36    // adjC [m=64][n=32]    A-op: r4*36 + c4        -> r4*4+c4 distinct
#define P_K  136   // K    [d=64][u=128]   B-op: c4*136 + r4       -> c4*8+r4 distinct
#define P_X1 68    // X1   [m=64][d=64]    A-op: r4*68 + c4        -> r4*4+c4 distinct

// smem layout in float words: F^T | 3 adj chunk bufs | K | X1
#define OFF_FT 0
#define OFF_AC (OFF_FT + ATOM * P_FT)        // 8448
#define OFF_K  (OFF_AC + 3 * MHALF * P_AC)   // 15360
#define OFF_X1 (OFF_K + ATOM * P_K)          // 24064
#define SMEM_WORDS (OFF_X1 + MHALF * P_X1)   // 28416
#define SMEM_BYTES (SMEM_WORDS * 4)          // 113664  (x2 CTAs = 227328 <= 228KB/SM)

__device__ __forceinline__ float f2tf32f(float f) {
    uint32_t u;
    asm("cvt.rna.tf32.f32 %0, %1;" : "=r"(u) : "f"(f));
    return __uint_as_float(u);
}

__device__ __forceinline__ void mma_tf32(float c[4], const uint32_t a[4], const uint32_t b[2]) {
    asm volatile(
        "mma.sync.aligned.m16n8k8.row.col.f32.tf32.tf32.f32 "
        "{%0,%1,%2,%3}, {%4,%5,%6,%7}, {%8,%9}, {%0,%1,%2,%3};"
        : "+f"(c[0]), "+f"(c[1]), "+f"(c[2]), "+f"(c[3])
        : "r"(a[0]), "r"(a[1]), "r"(a[2]), "r"(a[3]), "r"(b[0]), "r"(b[1]));
}

__device__ __forceinline__ uint32_t smem_u32(const void* p) {
    uint32_t a;
    asm("{ .reg .u64 t; cvta.to.shared.u64 t, %1; cvt.u32.u64 %0, t; }" : "=r"(a) : "l"(p));
    return a;
}
__device__ __forceinline__ void cpa16(uint32_t s, const float4* g) {
    asm volatile("cp.async.cg.shared.global [%0], [%1], 16;" :: "r"(s), "l"(g) : "memory");
}
#define CP_COMMIT() asm volatile("cp.async.commit_group;" ::: "memory")
template<int N> __device__ __forceinline__ void cp_wait() {
    asm volatile("cp.async.wait_group %0;" :: "n"(N) : "memory");
}

__device__ __forceinline__ float sel4(float a0, float a1, float a2, float a3, int idx) {
    float x = (idx & 1) ? a1 : a0;
    float y = (idx & 1) ? a3 : a2;
    return (idx & 2) ? y : x;
}
// 4x4 transpose in a 4-lane group: lane p holds M[row0+p][c0..c0+3] -> bb[j]=M[row0+j][c0+p]
__device__ __forceinline__ void xpose4(float4 v, int p, float bb[4]) {
    float r0 = sel4(v.x, v.y, v.z, v.w, p ^ 0);
    float r1 = __shfl_xor_sync(0xffffffffu, sel4(v.x, v.y, v.z, v.w, p ^ 1), 1);
    float r2 = __shfl_xor_sync(0xffffffffu, sel4(v.x, v.y, v.z, v.w, p ^ 2), 2);
    float r3 = __shfl_xor_sync(0xffffffffu, sel4(v.x, v.y, v.z, v.w, p ^ 3), 3);
    bb[0] = sel4(r0, r1, r2, r3, p ^ 0);
    bb[1] = sel4(r0, r1, r2, r3, p ^ 1);
    bb[2] = sel4(r0, r1, r2, r3, p ^ 2);
    bb[3] = sel4(r0, r1, r2, r3, p ^ 3);
}

__global__ void __launch_bounds__(THREADS, 2)
rgc_kernel(const float* __restrict__ adjacency,
           const float* __restrict__ features,
           const float* __restrict__ kern,
           float* __restrict__ out) {
    extern __shared__ float sm[];
    float* sFT = sm + OFF_FT;
    float* sAC = sm + OFF_AC;      // 3 buffers of MHALF*P_AC
    float* sK  = sm + OFF_K;
    float* sX1 = sm + OFF_X1;

    const uint32_t smb  = smem_u32(sm);
    const uint32_t sACB = smb + OFF_AC * 4u;
    const uint32_t sKB  = smb + OFF_K * 4u;

    const int tid = threadIdx.x;
    const int wid = tid >> 5;
    const int lid = tid & 31;
    const int r4  = lid >> 2;
    const int c4  = lid & 3;
    const int b   = blockIdx.x >> 1;
    const int mh  = (blockIdx.x & 1) << 6;   // 0 or 64

    // warp tiling: 2 m-tiles(32) x 4 n-tiles
    const int m0 = (wid & 1) * 32;           // M tile base (both GEMMs), within MHALF
    const int d0 = (wid >> 1) * 16;          // GEMM1 N(=atom) tile base
    const int u0 = (wid >> 1) * 32;          // GEMM2 N(=units) tile base

    const float4* adjB  = reinterpret_cast<const float4*>(adjacency) + (size_t)(b * BOND) * 4096;
    const float4* kerB  = reinterpret_cast<const float4*>(kern)      + (size_t)(b * BOND) * 2048;
    const float4* featB = reinterpret_cast<const float4*>(features)  + (size_t)b * 2048;

    // stage adjacency chunk g (bond g>>2, cols (g&3)*32..+32, rows mh..mh+63) -> buffer g%3
    auto stage_chunk = [&](int g) {
        const float4* src = adjB + (size_t)(g >> 2) * 4096;
        const int cc = (g & 3) * 8;
        uint32_t dst = sACB + (uint32_t)((g % 3) * MHALF * P_AC) * 4u;
        #pragma unroll
        for (int t = 0; t < 2; t++) {
            int i = tid + t * THREADS;          // 0..511
            int m = i >> 3, j = i & 7;
            cpa16(dst + (uint32_t)(m * P_AC + j * 4) * 4u,
                  src + (mh + m) * 32 + cc + j);
        }
    };
    auto stage_K = [&](int e) {
        const float4* src = kerB + (size_t)e * 2048;
        #pragma unroll
        for (int t = 0; t < 8; t++) {
            int i = tid + t * THREADS;          // 0..2047
            int dd = i >> 5, u4 = i & 31;
            cpa16(sKB + (uint32_t)(dd * P_K + u4 * 4) * 4u, src + i);
        }
    };

    // ---- prologue: F^T (shuffle-transpose, plain STS) + chunks 0,1 ----
    {
        // F[n=128][d=64] -> sFT[d][n] pitch 132
        #pragma unroll
        for (int t = wid; t < 64; t += 8) {
            int nb = t & 31, dbk = t >> 5;
            int n0 = nb * 4, dd0 = dbk * 32;
            float4 v = featB[(n0 + c4) * 16 + (dd0 >> 2) + r4];   // r4=0..7 -> d-offset 4*r4
            float bb[4];
            xpose4(v, c4, bb);                  // bb[j] = F[n0+j][dd0+4*r4+c4]
            int d = dd0 + 4 * r4 + c4;
            float* p = sFT + d * P_FT + n0;
            p[0] = bb[0]; p[1] = bb[1]; p[2] = bb[2]; p[3] = bb[3];
        }
        stage_chunk(0); CP_COMMIT();    // group {C0}
        stage_chunk(1); CP_COMMIT();    // group {C1}
    }

    float acc2[2][4][4];
    #pragma unroll
    for (int mt = 0; mt < 2; mt++)
        #pragma unroll
        for (int nt = 0; nt < 4; nt++)
            #pragma unroll
            for (int k = 0; k < 4; k++) acc2[mt][nt][k] = 0.0f;

    float acc1[2][2][4];
    // GEMM1 over one 32-col chunk in buffer sC; global n-base = c*32
    auto g1_chunk = [&](const float* sC, int c) {
        #pragma unroll
        for (int ks = 0; ks < 4; ks++) {
            const int kk = ks * 8;
            uint32_t a[2][4];
            #pragma unroll
            for (int mt = 0; mt < 2; mt++) {
                const float* pa = sC + (m0 + mt * 16 + r4) * P_AC + kk + c4;
                a[mt][0] = __float_as_uint(pa[0]);           // raw fp32 (HW tf32 trunc)
                a[mt][1] = __float_as_uint(pa[8 * P_AC]);
                a[mt][2] = __float_as_uint(pa[4]);
                a[mt][3] = __float_as_uint(pa[8 * P_AC + 4]);
            }
            uint32_t bf[2][2];
            #pragma unroll
            for (int nt = 0; nt < 2; nt++) {
                const float* pb = sFT + (d0 + nt * 8 + r4) * P_FT + c * 32 + kk + c4;
                bf[nt][0] = __float_as_uint(f2tf32f(pb[0]));
                bf[nt][1] = __float_as_uint(f2tf32f(pb[4]));
            }
            #pragma unroll
            for (int mt = 0; mt < 2; mt++)
                #pragma unroll
                for (int nt = 0; nt < 2; nt++)
                    mma_tf32(acc1[mt][nt], a[mt], bf[nt]);
        }
    };

    // FIFO group accounting (steady state, bond e, bars indexed by chunk g=4e+c):
    //   commits: at bar(e,0): {C(4e+2), K(e)}; at bar(e,c>0): {C(4e+c+2)}   (guard g<=19)
    //   waits:   every chunk bar waits<1> (2 groups in flight), except g==19 waits<0>
    //   => chunk g ready at its bar; K(e) drained by bar(e,2) < GEMM2(e); buffers rotate mod 3
    #pragma unroll 1
    for (int e = 0; e < BOND; e++) {
        #pragma unroll
        for (int mt = 0; mt < 2; mt++)
            #pragma unroll
            for (int nt = 0; nt < 2; nt++)
                #pragma unroll
                for (int k = 0; k < 4; k++) acc1[mt][nt][k] = 0.0f;

        #pragma unroll
        for (int c = 0; c < 4; c++) {
            const int g = e * 4 + c;
            if (e == BOND - 1 && c == 3) cp_wait<0>(); else cp_wait<1>();
            __syncthreads();   // chunk g visible; chunk g-1 consumed by all warps
            if (c == 0) {
                if (g + 2 <= 4 * BOND - 1) stage_chunk(g + 2);
                stage_K(e);
                CP_COMMIT();
            } else if (g + 2 <= 4 * BOND - 1) {
                stage_chunk(g + 2);
                CP_COMMIT();
            }
            g1_chunk(sAC + (g % 3) * MHALF * P_AC, c);
        }

        // ---- X1 -> smem, pre-rounded tf32 ----
        #pragma unroll
        for (int mt = 0; mt < 2; mt++) {
            #pragma unroll
            for (int nt = 0; nt < 2; nt++) {
                const int row = m0 + mt * 16 + r4;
                const int col = d0 + nt * 8 + 2 * c4;
                *reinterpret_cast<float2*>(sX1 + row * P_X1 + col) =
                    make_float2(f2tf32f(acc1[mt][nt][0]), f2tf32f(acc1[mt][nt][1]));
                *reinterpret_cast<float2*>(sX1 + (row + 8) * P_X1 + col) =
                    make_float2(f2tf32f(acc1[mt][nt][2]), f2tf32f(acc1[mt][nt][3]));
            }
        }
        __syncthreads();   // X1 visible (K(e) already drained at bar(e,2))

        // ---- GEMM2: OUT[m,u] += sum_d X1[m,d]*K[d,u]; warp tile 32x32 ----
        #pragma unroll 2
        for (int ks = 0; ks < 8; ks++) {
            const int kk = ks * 8;
            uint32_t a[2][4];
            #pragma unroll
            for (int mt = 0; mt < 2; mt++) {
                const float* pa = sX1 + (m0 + mt * 16 + r4) * P_X1 + kk + c4;
                a[mt][0] = __float_as_uint(pa[0]);       // already tf32-rounded
                a[mt][1] = __float_as_uint(pa[8 * P_X1]);
                a[mt][2] = __float_as_uint(pa[4]);
                a[mt][3] = __float_as_uint(pa[8 * P_X1 + 4]);
            }
            uint32_t bf[4][2];
            #pragma unroll
            for (int nt = 0; nt < 4; nt++) {
                const float* pb = sK + (kk + c4) * P_K + u0 + nt * 8 + r4;
                bf[nt][0] = __float_as_uint(f2tf32f(pb[0]));
                bf[nt][1] = __float_as_uint(f2tf32f(pb[4 * P_K]));
            }
            #pragma unroll
            for (int mt = 0; mt < 2; mt++)
                #pragma unroll
                for (int nt = 0; nt < 4; nt++)
                    mma_tf32(acc2[mt][nt], a[mt], bf[nt]);
        }
        // next bond's first chunk bar orders X1/K/adj reuse
    }

    // ---- epilogue: ReLU + store OUT[b][mh+m][u] ----
    float* ob = out + (size_t)b * (NDIM * UNITS) + (size_t)mh * UNITS;
    #pragma unroll
    for (int mt = 0; mt < 2; mt++) {
        #pragma unroll
        for (int nt = 0; nt < 4; nt++) {
            const int row = m0 + mt * 16 + r4;
            const int col = u0 + nt * 8 + 2 * c4;
            float2 v0 = make_float2(fmaxf(acc2[mt][nt][0], 0.0f), fmaxf(acc2[mt][nt][1], 0.0f));
            float2 v1 = make_float2(fmaxf(acc2[mt][nt][2], 0.0f), fmaxf(acc2[mt][nt][3], 0.0f));
            *reinterpret_cast<float2*>(ob + row * UNITS + col)       = v0;
            *reinterpret_cast<float2*>(ob + (row + 8) * UNITS + col) = v1;
        }
    }
}

extern "C" void kernel_launch(void* const* d_in, const int* in_sizes, int n_in,
                              void* d_out, int out_size) {
    const float* adj  = nullptr;
    const float* feat = nullptr;
    const float* ker  = nullptr;
    for (int i = 0; i < n_in; i++) {
        if      (in_sizes[i] == BSZ * BOND * NDIM * NDIM)  adj  = (const float*)d_in[i];
        else if (in_sizes[i] == BSZ * NDIM * ATOM)         feat = (const float*)d_in[i];
        else if (in_sizes[i] == BSZ * BOND * ATOM * UNITS) ker  = (const float*)d_in[i];
    }
    if (!adj)  adj  = (const float*)d_in[0];
    if (!feat) feat = (const float*)d_in[1];
    if (!ker)  ker  = (const float*)d_in[2];

    cudaFuncSetAttribute(rgc_kernel, cudaFuncAttributeMaxDynamicSharedMemorySize, SMEM_BYTES);
    rgc_kernel<<<BSZ * 2, THREADS, SMEM_BYTES>>>(adj, feat, ker, (float*)d_out);
}

// round 7
// speedup vs baseline: 1.0032x; 1.0032x over previous
#include <cuda_runtime.h>
#include <cstdint>

#define BSZ    256
#define BOND   5
#define NDIM   128
#define ATOM   64
#define UNITS  128
#define THREADS 256

// pitches (float words). Fragment-read pitches must be ==8 mod 32 for LDS.64
// phase-conflict-freedom; P_ADJ/P_KR are 4 mod 32 (scalar LDS.32 / LDS.128 paths).
#define P_FT  136   // F^T  [d=64][n=128 pair-permuted]
#define P_ADJ 132   // adj  [m=128][n=128]            (scalar A-op, as R5)
#define P_KR  132   // K raw [d=64][u=128]            (cp.async dst, LDS.128 src)
#define P_KT  72    // K^T  [u=128][d=64 pair-permuted]
#define P_X1  72    // X1   [m=128][d=64 pair-permuted]

#define OFF_FT  0
#define OFF_ADJ (OFF_FT  + ATOM * P_FT)    // 8704
#define OFF_KR  (OFF_ADJ + NDIM * P_ADJ)   // 25600
#define OFF_KT  (OFF_KR  + ATOM * P_KR)    // 34048
#define OFF_X1  (OFF_KT  + NDIM * P_KT)    // 43264
#define SMEM_WORDS (OFF_X1 + NDIM * P_X1)  // 52480
#define SMEM_BYTES (SMEM_WORDS * 4)        // 209920 (< 227328)

__device__ __forceinline__ float f2tf32f(float f) {
    uint32_t u;
    asm("cvt.rna.tf32.f32 %0, %1;" : "=r"(u) : "f"(f));
    return __uint_as_float(u);
}

__device__ __forceinline__ void mma_tf32(float c[4], const uint32_t a[4], const uint32_t b[2]) {
    asm volatile(
        "mma.sync.aligned.m16n8k8.row.col.f32.tf32.tf32.f32 "
        "{%0,%1,%2,%3}, {%4,%5,%6,%7}, {%8,%9}, {%0,%1,%2,%3};"
        : "+f"(c[0]), "+f"(c[1]), "+f"(c[2]), "+f"(c[3])
        : "r"(a[0]), "r"(a[1]), "r"(a[2]), "r"(a[3]), "r"(b[0]), "r"(b[1]));
}

__device__ __forceinline__ uint32_t smem_u32(const void* p) {
    uint32_t a;
    asm("{ .reg .u64 t; cvta.to.shared.u64 t, %1; cvt.u32.u64 %0, t; }" : "=r"(a) : "l"(p));
    return a;
}
__device__ __forceinline__ void cpa16(uint32_t s, const float4* g) {
    asm volatile("cp.async.cg.shared.global [%0], [%1], 16;" :: "r"(s), "l"(g) : "memory");
}
#define CP_COMMIT() asm volatile("cp.async.commit_group;" ::: "memory")
template<int N> __device__ __forceinline__ void cp_wait() {
    asm volatile("cp.async.wait_group %0;" :: "n"(N) : "memory");
}

// pair-interleave within an 8-group: c -> 2c (c<4), 2(c-4)+1 (c>=4)
__device__ __forceinline__ int perm8(int c) { return ((c & 3) << 1) | ((c >> 2) & 1); }
__device__ __forceinline__ int colperm(int d) { return (d & ~7) | perm8(d & 7); }

__device__ __forceinline__ float sel4(float a0, float a1, float a2, float a3, int idx) {
    float x = (idx & 1) ? a1 : a0;
    float y = (idx & 1) ? a3 : a2;
    return (idx & 2) ? y : x;
}
__device__ __forceinline__ void xpose4(float4 v, int p, float bb[4]) {
    float r0 = sel4(v.x, v.y, v.z, v.w, p ^ 0);
    float r1 = __shfl_xor_sync(0xffffffffu, sel4(v.x, v.y, v.z, v.w, p ^ 1), 1);
    float r2 = __shfl_xor_sync(0xffffffffu, sel4(v.x, v.y, v.z, v.w, p ^ 2), 2);
    float r3 = __shfl_xor_sync(0xffffffffu, sel4(v.x, v.y, v.z, v.w, p ^ 3), 3);
    bb[0] = sel4(r0, r1, r2, r3, p ^ 0);
    bb[1] = sel4(r0, r1, r2, r3, p ^ 1);
    bb[2] = sel4(r0, r1, r2, r3, p ^ 2);
    bb[3] = sel4(r0, r1, r2, r3, p ^ 3);
}

__global__ void __launch_bounds__(THREADS, 1)
rgc_kernel(const float* __restrict__ adjacency,
           const float* __restrict__ features,
           const float* __restrict__ kern,
           float* __restrict__ out) {
    extern __shared__ float sm[];
    float* sFT = sm + OFF_FT;
    float* sAdj = sm + OFF_ADJ;
    float* sKR = sm + OFF_KR;
    float* sKT = sm + OFF_KT;
    float* sX1 = sm + OFF_X1;

    const uint32_t smb   = smem_u32(sm);
    const uint32_t sAdjB = smb + OFF_ADJ * 4u;
    const uint32_t sKRB  = smb + OFF_KR * 4u;

    const int tid = threadIdx.x;
    const int wid = tid >> 5;
    const int lid = tid & 31;
    const int r4  = lid >> 2;
    const int c4  = lid & 3;
    const int b   = blockIdx.x;

    const int m0 = (wid & 3) * 32;       // M tile base (both GEMMs)
    const int d0 = (wid >> 2) * 32;      // GEMM1 N(=atom) tile base
    const int u0 = (wid >> 2) * 64;      // GEMM2 N(=units) tile base
    const int pc0 = perm8(2 * c4);       // X1-store permuted cols
    const int pc1 = perm8(2 * c4 + 1);

    const float4* adjB  = reinterpret_cast<const float4*>(adjacency) + (size_t)(b * BOND) * 4096;
    const float4* kerB  = reinterpret_cast<const float4*>(kern)      + (size_t)(b * BOND) * 2048;
    const float4* featB = reinterpret_cast<const float4*>(features)  + (size_t)b * 2048;

    auto stage_chunk = [&](int e, int c) {
        const float4* src = adjB + (size_t)e * 4096;
        #pragma unroll
        for (int t = 0; t < 4; t++) {
            int i = tid + t * THREADS;          // 0..1023
            int m = i >> 3, j = i & 7;
            cpa16(sAdjB + (uint32_t)(m * P_ADJ + (c * 8 + j) * 4) * 4u,
                  src + m * 32 + c * 8 + j);
        }
    };
    auto stage_K = [&](int e) {
        const float4* src = kerB + (size_t)e * 2048;
        #pragma unroll
        for (int t = 0; t < 8; t++) {
            int i = tid + t * THREADS;          // 0..2047
            int dd = i >> 5, u4 = i & 31;
            cpa16(sKRB + (uint32_t)(dd * P_KR + u4 * 4) * 4u, src + i);
        }
    };

    // ---- prologue: F^T (LDG + xpose + cvt + permuted STS), then cp.async groups ----
    {
        for (int t = wid; t < 64; t += 8) {
            int nb = t & 31, dbk = t >> 5;
            int n0 = nb * 4, dd0 = dbk * 32;
            float4 v = featB[(n0 + c4) * 16 + dbk * 8 + r4];
            float bb[4];
            xpose4(v, c4, bb);                  // bb[j] = F[n0+j][dd0+4*r4+c4]
            int d = dd0 + 4 * r4 + c4;
            int ncb = (n0 & ~7) | ((n0 >> 2) & 1);   // permuted col base; cols ncb+2j
            float* p = sFT + d * P_FT + ncb;
            p[0] = f2tf32f(bb[0]); p[2] = f2tf32f(bb[1]);
            p[4] = f2tf32f(bb[2]); p[6] = f2tf32f(bb[3]);
        }
        stage_K(0); stage_chunk(0, 0); CP_COMMIT();   // group {K0, C0}
        stage_chunk(0, 1); CP_COMMIT();
        stage_chunk(0, 2); CP_COMMIT();
        stage_chunk(0, 3); CP_COMMIT();
    }

    float acc2[2][8][4];
    #pragma unroll
    for (int mt = 0; mt < 2; mt++)
        #pragma unroll
        for (int nt = 0; nt < 8; nt++)
            #pragma unroll
            for (int k = 0; k < 4; k++) acc2[mt][nt][k] = 0.0f;

    float acc1[2][4][4];
    auto g1_chunk = [&](int c) {
        #pragma unroll
        for (int ks = 0; ks < 4; ks++) {
            const int k0 = c * 32 + ks * 8;
            uint32_t a[2][4];
            #pragma unroll
            for (int mt = 0; mt < 2; mt++) {
                const float* pa = sAdj + (m0 + mt * 16 + r4) * P_ADJ + k0 + c4;
                a[mt][0] = __float_as_uint(pa[0]);           // raw fp32 (HW tf32 trunc)
                a[mt][1] = __float_as_uint(pa[8 * P_ADJ]);
                a[mt][2] = __float_as_uint(pa[4]);
                a[mt][3] = __float_as_uint(pa[8 * P_ADJ + 4]);
            }
            uint32_t bf[4][2];
            #pragma unroll
            for (int nt = 0; nt < 4; nt++) {
                float2 v = *reinterpret_cast<const float2*>(
                    sFT + (d0 + nt * 8 + r4) * P_FT + k0 + 2 * c4);  // pre-cvt'd
                bf[nt][0] = __float_as_uint(v.x);
                bf[nt][1] = __float_as_uint(v.y);
            }
            #pragma unroll
            for (int mt = 0; mt < 2; mt++)
                #pragma unroll
                for (int nt = 0; nt < 4; nt++)
                    mma_tf32(acc1[mt][nt], a[mt], bf[nt]);
        }
    };

    #pragma unroll 1
    for (int e = 0; e < BOND; e++) {
        #pragma unroll
        for (int mt = 0; mt < 2; mt++)
            #pragma unroll
            for (int nt = 0; nt < 4; nt++)
                #pragma unroll
                for (int k = 0; k < 4; k++) acc1[mt][nt][k] = 0.0f;

        // c=0: {K(e),C0} landed; transpose K(e) raw -> K^T (cvt once), then GEMM1 chunk0
        cp_wait<3>(); __syncthreads();
        {
            const int dd  = ((wid & 1) << 5) + lid;        // 0..63
            const int ufb = (wid >> 1) << 3;               // u-float4 base
            const int cp  = colperm(dd);
            const float* srcr = sKR + dd * P_KR;
            #pragma unroll
            for (int it = 0; it < 8; it++) {
                const int uf = ufb + it;
                float4 v = *reinterpret_cast<const float4*>(srcr + uf * 4);
                float* dst = sKT + (4 * uf) * P_KT + cp;
                dst[0]        = f2tf32f(v.x);
                dst[P_KT]     = f2tf32f(v.y);
                dst[2 * P_KT] = f2tf32f(v.z);
                dst[3 * P_KT] = f2tf32f(v.w);
            }
        }
        g1_chunk(0);
        cp_wait<2>(); __syncthreads(); g1_chunk(1);
        cp_wait<1>(); __syncthreads(); g1_chunk(2);
        cp_wait<0>(); __syncthreads(); g1_chunk(3);

        // ---- X1 -> smem, tf32-rounded, pair-permuted d cols ----
        #pragma unroll
        for (int mt = 0; mt < 2; mt++) {
            #pragma unroll
            for (int nt = 0; nt < 4; nt++) {
                const int row = m0 + mt * 16 + r4;
                float* p0 = sX1 + row * P_X1 + d0 + nt * 8;
                float* p1 = sX1 + (row + 8) * P_X1 + d0 + nt * 8;
                p0[pc0] = f2tf32f(acc1[mt][nt][0]);
                p0[pc1] = f2tf32f(acc1[mt][nt][1]);
                p1[pc0] = f2tf32f(acc1[mt][nt][2]);
                p1[pc1] = f2tf32f(acc1[mt][nt][3]);
            }
        }
        __syncthreads();   // X1 + K^T visible to all; adj fully consumed

        // ---- prefetch bond e+1: {K',C0'},{C1'},{C2'},{C3'} (fly during GEMM2) ----
        if (e + 1 < BOND) {
            stage_K(e + 1); stage_chunk(e + 1, 0); CP_COMMIT();
            stage_chunk(e + 1, 1); CP_COMMIT();
            stage_chunk(e + 1, 2); CP_COMMIT();
            stage_chunk(e + 1, 3); CP_COMMIT();
        }

        // ---- GEMM2: OUT[m,u] += sum_d X1[m,d]*K[d,u]; warp tile 32x64, all LDS.64 ----
        #pragma unroll 2
        for (int ks = 0; ks < 8; ks++) {
            const int k0 = ks * 8;
            uint32_t a[2][4];
            #pragma unroll
            for (int mt = 0; mt < 2; mt++) {
                const int row = m0 + mt * 16 + r4;
                float2 lo = *reinterpret_cast<const float2*>(sX1 + row * P_X1 + k0 + 2 * c4);
                float2 hi = *reinterpret_cast<const float2*>(sX1 + (row + 8) * P_X1 + k0 + 2 * c4);
                a[mt][0] = __float_as_uint(lo.x);
                a[mt][1] = __float_as_uint(hi.x);
                a[mt][2] = __float_as_uint(lo.y);
                a[mt][3] = __float_as_uint(hi.y);
            }
            uint32_t bf[8][2];
            #pragma unroll
            for (int nt = 0; nt < 8; nt++) {
                float2 v = *reinterpret_cast<const float2*>(
                    sKT + (u0 + nt * 8 + r4) * P_KT + k0 + 2 * c4);
                bf[nt][0] = __float_as_uint(v.x);
                bf[nt][1] = __float_as_uint(v.y);
            }
            #pragma unroll
            for (int mt = 0; mt < 2; mt++)
                #pragma unroll
                for (int nt = 0; nt < 8; nt++)
                    mma_tf32(acc2[mt][nt], a[mt], bf[nt]);
        }
        // next bond's c=0 barrier orders reuse of X1 / K^T / adj
    }

    // ---- epilogue: ReLU + store OUT[b][m][u] ----
    float* ob = out + (size_t)b * (NDIM * UNITS);
    #pragma unroll
    for (int mt = 0; mt < 2; mt++) {
        #pragma unroll
        for (int nt = 0; nt < 8; nt++) {
            const int row = m0 + mt * 16 + r4;
            const int col = u0 + nt * 8 + 2 * c4;
            float2 v0 = make_float2(fmaxf(acc2[mt][nt][0], 0.0f), fmaxf(acc2[mt][nt][1], 0.0f));
            float2 v1 = make_float2(fmaxf(acc2[mt][nt][2], 0.0f), fmaxf(acc2[mt][nt][3], 0.0f));
            *reinterpret_cast<float2*>(ob + row * UNITS + col)       = v0;
            *reinterpret_cast<float2*>(ob + (row + 8) * UNITS + col) = v1;
        }
    }
}

extern "C" void kernel_launch(void* const* d_in, const int* in_sizes, int n_in,
                              void* d_out, int out_size) {
    const float* adj  = nullptr;
    const float* feat = nullptr;
    const float* ker  = nullptr;
    for (int i = 0; i < n_in; i++) {
        if      (in_sizes[i] == BSZ * BOND * NDIM * NDIM)  adj  = (const float*)d_in[i];
        else if (in_sizes[i] == BSZ * NDIM * ATOM)         feat = (const float*)d_in[i];
        else if (in_sizes[i] == BSZ * BOND * ATOM * UNITS) ker  = (const float*)d_in[i];
    }
    if (!adj)  adj  = (const float*)d_in[0];
    if (!feat) feat = (const float*)d_in[1];
    if (!ker)  ker  = (const float*)d_in[2];

    cudaFuncSetAttribute(rgc_kernel, cudaFuncAttributeMaxDynamicSharedMemorySize, SMEM_BYTES);
    rgc_kernel<<<BSZ, THREADS, SMEM_BYTES>>>(adj, feat, ker, (float*)d_out);
}

// round 8
// speedup vs baseline: 1.1628x; 1.1591x over previous
#include <cuda_runtime.h>
#include <cstdint>

#define BSZ    256
#define BOND   5
#define NDIM   128
#define ATOM   64
#define UNITS  128
#define THREADS 256

// smem float-word pitches (conflict-free fragment access; pitch % 32 == 4 or 8)
#define P_F    72    // F   [n=128][d=64]   (pre-rounded tf32 at staging)
#define P_ADJ  132   // adj [m=128][n=128]
#define P_K    136   // K   [d=64][u=128]
#define P_X1   68    // X1  [m=128][d=64]

// smem layout in float words: F | adj | K0 | K1 | X1
#define OFF_F    0
#define OFF_ADJ  (OFF_F   + NDIM * P_F)     // 9216
#define OFF_K0   (OFF_ADJ + NDIM * P_ADJ)   // 26112
#define OFF_K1   (OFF_K0  + ATOM * P_K)     // 34816
#define OFF_X1   (OFF_K1  + ATOM * P_K)     // 43520
#define SMEM_WORDS (OFF_X1 + NDIM * P_X1)   // 52224
#define SMEM_BYTES (SMEM_WORDS * 4)         // 208896 (< 227KB)

__device__ __forceinline__ float f2tf32f(float f) {
    uint32_t u;
    asm("cvt.rna.tf32.f32 %0, %1;" : "=r"(u) : "f"(f));
    return __uint_as_float(u);
}

__device__ __forceinline__ void mma_tf32(float c[4], const uint32_t a[4], const uint32_t b[2]) {
    asm volatile(
        "mma.sync.aligned.m16n8k8.row.col.f32.tf32.tf32.f32 "
        "{%0,%1,%2,%3}, {%4,%5,%6,%7}, {%8,%9}, {%0,%1,%2,%3};"
        : "+f"(c[0]), "+f"(c[1]), "+f"(c[2]), "+f"(c[3])
        : "r"(a[0]), "r"(a[1]), "r"(a[2]), "r"(a[3]), "r"(b[0]), "r"(b[1]));
}

__device__ __forceinline__ uint32_t smem_u32(const void* p) {
    uint32_t a;
    asm("{ .reg .u64 t; cvta.to.shared.u64 t, %1; cvt.u32.u64 %0, t; }" : "=r"(a) : "l"(p));
    return a;
}
__device__ __forceinline__ void cpa16(uint32_t s, const float4* g) {
    asm volatile("cp.async.cg.shared.global [%0], [%1], 16;" :: "r"(s), "l"(g) : "memory");
}
#define CP_COMMIT() asm volatile("cp.async.commit_group;" ::: "memory")
template<int N> __device__ __forceinline__ void cp_wait() {
    asm volatile("cp.async.wait_group %0;" :: "n"(N) : "memory");
}

__global__ void __launch_bounds__(THREADS, 1)
rgc_kernel(const float* __restrict__ adjacency,
           const float* __restrict__ features,
           const float* __restrict__ kern,
           float* __restrict__ out) {
    extern __shared__ float sm[];
    float* sF   = sm + OFF_F;
    float* sAdj = sm + OFF_ADJ;
    float* sK0  = sm + OFF_K0;
    float* sK1  = sm + OFF_K1;
    float* sX1  = sm + OFF_X1;

    const uint32_t smb   = smem_u32(sm);
    const uint32_t sAdjB = smb + OFF_ADJ * 4u;
    const uint32_t sK0B  = smb + OFF_K0 * 4u;
    const uint32_t sK1B  = smb + OFF_K1 * 4u;

    const int tid = threadIdx.x;
    const int wid = tid >> 5;
    const int lid = tid & 31;
    const int r4  = lid >> 2;
    const int c4  = lid & 3;
    const int b   = blockIdx.x;

    const int m0 = (wid & 3) * 32;       // M tile base (both GEMMs)
    const int d0 = (wid >> 2) * 32;      // GEMM1 N (=atom) tile base
    const int u0 = (wid >> 2) * 64;      // GEMM2 N (=units) tile base

    const float4* adjB  = reinterpret_cast<const float4*>(adjacency) + (size_t)(b * BOND) * 4096;
    const float4* kerB  = reinterpret_cast<const float4*>(kern)      + (size_t)(b * BOND) * 2048;
    const float4* featB = reinterpret_cast<const float4*>(features)  + (size_t)b * 2048;

    auto stage_adj_chunk = [&](const float4* src, int c) {
        #pragma unroll
        for (int t = 0; t < 4; t++) {
            int i = tid + t * THREADS;          // 0..1023
            int m = i >> 3, j = i & 7;
            cpa16(sAdjB + (uint32_t)(m * P_ADJ + (c * 8 + j) * 4) * 4u,
                  src + m * 32 + c * 8 + j);
        }
    };
    auto stage_K = [&](uint32_t dstB, const float4* src) {
        #pragma unroll
        for (int t = 0; t < 8; t++) {
            int i = tid + t * THREADS;          // 0..2047
            int dd = i >> 5, u4 = i & 31;
            cpa16(dstB + (uint32_t)(dd * P_K + u4 * 4) * 4u, src + i);
        }
    };

    // ---- prologue: F via LDG+cvt+STS (pre-rounded, off critical path), then cp.async groups ----
    {
        #pragma unroll
        for (int t = 0; t < 8; t++) {
            int i = tid + t * THREADS;          // 0..2047
            float4 v = featB[i];
            int node = i >> 4, a4 = i & 15;
            float* d = sF + node * P_F + a4 * 4;
            d[0] = f2tf32f(v.x); d[1] = f2tf32f(v.y);
            d[2] = f2tf32f(v.z); d[3] = f2tf32f(v.w);
        }
        stage_adj_chunk(adjB, 0); CP_COMMIT();
        stage_adj_chunk(adjB, 1); CP_COMMIT();
        stage_adj_chunk(adjB, 2); CP_COMMIT();
        stage_adj_chunk(adjB, 3); CP_COMMIT();
        stage_K(sK0B, kerB);      CP_COMMIT();
    }

    float acc2[2][8][4];
    #pragma unroll
    for (int mt = 0; mt < 2; mt++)
        #pragma unroll
        for (int nt = 0; nt < 8; nt++)
            #pragma unroll
            for (int k = 0; k < 4; k++) acc2[mt][nt][k] = 0.0f;

    float acc1[2][4][4];

    // ---- fragment loaders (G1) ----
    auto load_g1 = [&](int c, int ks, uint32_t (&a)[2][4], uint32_t (&bf)[4][2]) {
        const int k0 = c * 32 + ks * 8;
        #pragma unroll
        for (int mt = 0; mt < 2; mt++) {
            const float* pa = sAdj + (m0 + mt * 16 + r4) * P_ADJ + k0 + c4;
            a[mt][0] = __float_as_uint(pa[0]);           // raw fp32 (HW tf32 trunc)
            a[mt][1] = __float_as_uint(pa[8 * P_ADJ]);
            a[mt][2] = __float_as_uint(pa[4]);
            a[mt][3] = __float_as_uint(pa[8 * P_ADJ + 4]);
        }
        #pragma unroll
        for (int nt = 0; nt < 4; nt++) {
            const float* pb = sF + (k0 + c4) * P_F + d0 + nt * 8 + r4;
            bf[nt][0] = __float_as_uint(pb[0]);          // pre-rounded at staging
            bf[nt][1] = __float_as_uint(pb[4 * P_F]);
        }
    };

    // software-pipelined GEMM1 chunk: loads for ks+1 issue before mmas of ks
    auto g1_chunk = [&](int c) {
        uint32_t a[2][2][4], bf[2][4][2];
        load_g1(c, 0, a[0], bf[0]);
        #pragma unroll
        for (int ks = 0; ks < 4; ks++) {
            if (ks < 3) load_g1(c, ks + 1, a[(ks + 1) & 1], bf[(ks + 1) & 1]);
            #pragma unroll
            for (int mt = 0; mt < 2; mt++)
                #pragma unroll
                for (int nt = 0; nt < 4; nt++)
                    mma_tf32(acc1[mt][nt], a[ks & 1][mt], bf[ks & 1][nt]);
        }
    };

    #pragma unroll 1
    for (int e = 0; e < BOND; e++) {
        #pragma unroll
        for (int mt = 0; mt < 2; mt++)
            #pragma unroll
            for (int nt = 0; nt < 4; nt++)
                #pragma unroll
                for (int k = 0; k < 4; k++) acc1[mt][nt][k] = 0.0f;

        // ---- GEMM1, chunk-pipelined against in-flight cp.async groups ----
        cp_wait<4>(); __syncthreads(); g1_chunk(0);
        cp_wait<3>(); __syncthreads(); g1_chunk(1);
        cp_wait<2>(); __syncthreads(); g1_chunk(2);
        cp_wait<1>(); __syncthreads(); g1_chunk(3);

        // ---- X1 -> smem, pre-rounded to tf32 (A operand of GEMM2) ----
        #pragma unroll
        for (int mt = 0; mt < 2; mt++) {
            #pragma unroll
            for (int nt = 0; nt < 4; nt++) {
                const int row = m0 + mt * 16 + r4;
                const int col = d0 + nt * 8 + 2 * c4;
                *reinterpret_cast<float2*>(sX1 + row * P_X1 + col) =
                    make_float2(f2tf32f(acc1[mt][nt][0]), f2tf32f(acc1[mt][nt][1]));
                *reinterpret_cast<float2*>(sX1 + (row + 8) * P_X1 + col) =
                    make_float2(f2tf32f(acc1[mt][nt][2]), f2tf32f(acc1[mt][nt][3]));
            }
        }
        cp_wait<0>();        // K(e) landed (adj(e) already consumed)
        __syncthreads();     // X1 visible; all GEMM1 reads of adj done

        // ---- prefetch bond e+1 (5 groups; fly during GEMM2) ----
        if (e + 1 < BOND) {
            const float4* adjN = adjB + (size_t)(e + 1) * 4096;
            stage_adj_chunk(adjN, 0); CP_COMMIT();
            stage_adj_chunk(adjN, 1); CP_COMMIT();
            stage_adj_chunk(adjN, 2); CP_COMMIT();
            stage_adj_chunk(adjN, 3); CP_COMMIT();
            stage_K((e & 1) ? sK0B : sK1B, kerB + (size_t)(e + 1) * 2048); CP_COMMIT();
        }

        // ---- GEMM2: OUT[m,u] += sum_d X1[m,d]*K[d,u]; warp tile 32x64, pipelined ----
        const float* sKe = (e & 1) ? sK1 : sK0;
        auto load_g2 = [&](int ks, uint32_t (&a)[2][4], uint32_t (&bf)[8][2]) {
            const int k0 = ks * 8;
            #pragma unroll
            for (int mt = 0; mt < 2; mt++) {
                const float* pa = sX1 + (m0 + mt * 16 + r4) * P_X1 + k0 + c4;
                a[mt][0] = __float_as_uint(pa[0]);       // already tf32-rounded
                a[mt][1] = __float_as_uint(pa[8 * P_X1]);
                a[mt][2] = __float_as_uint(pa[4]);
                a[mt][3] = __float_as_uint(pa[8 * P_X1 + 4]);
            }
            #pragma unroll
            for (int nt = 0; nt < 8; nt++) {
                const float* pb = sKe + (k0 + c4) * P_K + u0 + nt * 8 + r4;
                bf[nt][0] = __float_as_uint(f2tf32f(pb[0]));
                bf[nt][1] = __float_as_uint(f2tf32f(pb[4 * P_K]));
            }
        };
        {
            uint32_t a[2][2][4], bf[2][8][2];
            load_g2(0, a[0], bf[0]);
            #pragma unroll
            for (int ks = 0; ks < 8; ks++) {
                if (ks < 7) load_g2(ks + 1, a[(ks + 1) & 1], bf[(ks + 1) & 1]);
                #pragma unroll
                for (int mt = 0; mt < 2; mt++)
                    #pragma unroll
                    for (int nt = 0; nt < 8; nt++)
                        mma_tf32(acc2[mt][nt], a[ks & 1][mt], bf[ks & 1][nt]);
            }
        }
        // next bond's first chunk bar orders X1/adj reuse
    }

    // ---- epilogue: ReLU + store OUT[b][m][u] ----
    float* ob = out + (size_t)b * (NDIM * UNITS);
    #pragma unroll
    for (int mt = 0; mt < 2; mt++) {
        #pragma unroll
        for (int nt = 0; nt < 8; nt++) {
            const int row = m0 + mt * 16 + r4;
            const int col = u0 + nt * 8 + 2 * c4;
            float2 v0 = make_float2(fmaxf(acc2[mt][nt][0], 0.0f), fmaxf(acc2[mt][nt][1], 0.0f));
            float2 v1 = make_float2(fmaxf(acc2[mt][nt][2], 0.0f), fmaxf(acc2[mt][nt][3], 0.0f));
            *reinterpret_cast<float2*>(ob + row * UNITS + col)       = v0;
            *reinterpret_cast<float2*>(ob + (row + 8) * UNITS + col) = v1;
        }
    }
}

extern "C" void kernel_launch(void* const* d_in, const int* in_sizes, int n_in,
                              void* d_out, int out_size) {
    const float* adj  = nullptr;
    const float* feat = nullptr;
    const float* ker  = nullptr;
    for (int i = 0; i < n_in; i++) {
        if      (in_sizes[i] == BSZ * BOND * NDIM * NDIM)  adj  = (const float*)d_in[i];
        else if (in_sizes[i] == BSZ * NDIM * ATOM)         feat = (const float*)d_in[i];
        else if (in_sizes[i] == BSZ * BOND * ATOM * UNITS) ker  = (const float*)d_in[i];
    }
    if (!adj)  adj  = (const float*)d_in[0];
    if (!feat) feat = (const float*)d_in[1];
    if (!ker)  ker  = (const float*)d_in[2];

    cudaFuncSetAttribute(rgc_kernel, cudaFuncAttributeMaxDynamicSharedMemorySize, SMEM_BYTES);
    rgc_kernel<<<BSZ, THREADS, SMEM_BYTES>>>(adj, feat, ker, (float*)d_out);
}